// round 14
// baseline (speedup 1.0000x reference)
#include <cuda_runtime.h>

#define BATCH 65536
#define SEQ 54
#define DIM 6
#define NB 8
#define TPI 18               // threads per item (3 queries each)
#define GG 7                 // items per CTA
#define TPB (GG * TPI)       // 126 threads
#define GRID ((BATCH + GG - 1) / GG)   // 9363
#define KV_STRIDE 660        // floats per item slot (16B-aligned, bank step 20)

typedef unsigned long long u64;

__device__ __forceinline__ float ex2f(float x) {
    float r; asm("ex2.approx.ftz.f32 %0, %1;" : "=f"(r) : "f"(x)); return r;
}
__device__ __forceinline__ u64 fma2(u64 a, u64 b, u64 c) {
    u64 d; asm("fma.rn.f32x2 %0, %1, %2, %3;" : "=l"(d) : "l"(a), "l"(b), "l"(c)); return d;
}
__device__ __forceinline__ u64 mul2(u64 a, u64 b) {
    u64 d; asm("mul.rn.f32x2 %0, %1, %2;" : "=l"(d) : "l"(a), "l"(b)); return d;
}
__device__ __forceinline__ u64 pack2(float lo, float hi) {
    u64 d; asm("mov.b64 %0, {%1, %2};" : "=l"(d)
               : "r"(__float_as_uint(lo)), "r"(__float_as_uint(hi))); return d;
}
__device__ __forceinline__ float2 unpack2(u64 d) {
    unsigned lo, hi; asm("mov.b64 {%0, %1}, %2;" : "=r"(lo), "=r"(hi) : "l"(d));
    return make_float2(__uint_as_float(lo), __uint_as_float(hi));
}
__device__ __forceinline__ float eluf(float x) { return x > 0.f ? x : (__expf(x) - 1.f); }

__global__ void __launch_bounds__(TPB, 6) rubik_kernel(
    const float* __restrict__ x,
    const float* __restrict__ embed_w, const float* __restrict__ embed_b,
    const float* __restrict__ fc1_w,   const float* __restrict__ fc1_b,
    const float* __restrict__ ln_g,    const float* __restrict__ ln_b,
    const float* __restrict__ ipw,     const float* __restrict__ ipb,
    const float* __restrict__ outw,    const float* __restrict__ outb,
    const float* __restrict__ value_w, const float* __restrict__ value_b,
    const float* __restrict__ policy_w,const float* __restrict__ policy_b,
    float* __restrict__ out)
{
    // output-pair-interleaved weights: s_*w2[..][i2][j] = (w[2*i2][j], w[2*i2+1][j])
    __shared__ __align__(16) float2 s_ew2[3][8];
    __shared__ __align__(16) float2 s_eb2[4];
    __shared__ __align__(16) float2 s_fw2[NB][3][8];
    __shared__ __align__(16) float2 s_fb2[NB][4];
    __shared__ float s_g [NB][8];
    __shared__ float s_bb[NB][8];
    __shared__ __align__(16) float2 s_iw2[NB][9][8];
    __shared__ __align__(16) float2 s_ib2[NB][12];
    __shared__ __align__(16) float2 s_ow2[NB][3][8];
    __shared__ __align__(16) float2 s_ob2[NB][4];
    __shared__ __align__(16) float s_kv[GG * KV_STRIDE];
    __shared__ float s_lg[GG][16];

    const int tid = threadIdx.x;

    // ---- cooperative weight staging (pair-interleaved) ----
    for (int i = tid; i < 18; i += TPB) {
        int i2 = i / 6, j = i % 6;
        s_ew2[i2][j] = make_float2(embed_w[(2*i2)*6 + j], embed_w[(2*i2+1)*6 + j]);
    }
    if (tid < 3) s_eb2[tid] = make_float2(embed_b[2*tid], embed_b[2*tid+1]);
    for (int i = tid; i < NB*18; i += TPB) {
        int blk = i / 18, r = i % 18, i2 = r / 6, j = r % 6;
        const float* w = fc1_w + blk * 36;
        s_fw2[blk][i2][j] = make_float2(w[(2*i2)*6 + j], w[(2*i2+1)*6 + j]);
    }
    for (int i = tid; i < NB*3; i += TPB) {
        int blk = i / 3, i2 = i % 3;
        s_fb2[blk][i2] = make_float2(fc1_b[blk*6 + 2*i2], fc1_b[blk*6 + 2*i2 + 1]);
    }
    for (int i = tid; i < NB*6; i += TPB) s_g [i/6][i%6] = ln_g[i];
    for (int i = tid; i < NB*6; i += TPB) s_bb[i/6][i%6] = ln_b[i];
    for (int i = tid; i < NB*54; i += TPB) {
        int blk = i / 54, r = i % 54, i2 = r / 6, j = r % 6;
        const float* w = ipw + blk * 108;
        s_iw2[blk][i2][j] = make_float2(w[(2*i2)*6 + j], w[(2*i2+1)*6 + j]);
    }
    for (int i = tid; i < NB*9; i += TPB) {
        int blk = i / 9, i2 = i % 9;
        s_ib2[blk][i2] = make_float2(ipb[blk*18 + 2*i2], ipb[blk*18 + 2*i2 + 1]);
    }
    for (int i = tid; i < NB*18; i += TPB) {
        int blk = i / 18, r = i % 18, i2 = r / 6, j = r % 6;
        const float* w = outw + blk * 36;
        s_ow2[blk][i2][j] = make_float2(w[(2*i2)*6 + j], w[(2*i2+1)*6 + j]);
    }
    for (int i = tid; i < NB*3; i += TPB) {
        int blk = i / 3, i2 = i % 3;
        s_ob2[blk][i2] = make_float2(outb[blk*6 + 2*i2], outb[blk*6 + 2*i2 + 1]);
    }
    __syncthreads();

    const int g    = tid / TPI;        // item slot within CTA
    const int t    = tid - g * TPI;    // query-thread index, tokens t, t+18, t+36
    const int item = blockIdx.x * GG + g;
    const bool live = (item < BATCH);
    float* kvbase = s_kv + g * KV_STRIDE;

    // fold softmax scale and log2(e) into q
    const float QS = 0.40824829046386302f * 1.4426950408889634f;
    const u64 QS2 = pack2(QS, QS);

    // ---- embed: h = x @ ew^T + eb (3 tokens, packed output pairs) ----
    float h[3][6];
    {
        u64 xs[3][6];
        #pragma unroll
        for (int tt = 0; tt < 3; tt++) {
            const float* xp = x + (item * SEQ + t + tt * TPI) * DIM;
            #pragma unroll
            for (int d = 0; d < 6; d++) {
                float v = live ? xp[d] : 0.f;
                xs[tt][d] = pack2(v, v);
            }
        }
        #pragma unroll
        for (int i2 = 0; i2 < 3; i2++) {
            const ulonglong2* wr = reinterpret_cast<const ulonglong2*>(&s_ew2[i2][0]);
            ulonglong2 w01 = wr[0], w23 = wr[1], w45 = wr[2];
            u64 b = *reinterpret_cast<const u64*>(&s_eb2[i2]);
            #pragma unroll
            for (int tt = 0; tt < 3; tt++) {
                u64 acc = b;
                acc = fma2(xs[tt][0], w01.x, acc); acc = fma2(xs[tt][1], w01.y, acc);
                acc = fma2(xs[tt][2], w23.x, acc); acc = fma2(xs[tt][3], w23.y, acc);
                acc = fma2(xs[tt][4], w45.x, acc); acc = fma2(xs[tt][5], w45.y, acc);
                float2 r = unpack2(acc);
                h[tt][2*i2] = r.x; h[tt][2*i2+1] = r.y;
            }
        }
    }

    for (int blk = 0; blk < NB; blk++) {
        u64 sp[3][6];   // splat buffer (h for fc1, then z for qkv, then ov for out)

        // ---- fc1 + ELU (packed output pairs, weights hoisted) ----
        float z[3][6];
        #pragma unroll
        for (int tt = 0; tt < 3; tt++)
            #pragma unroll
            for (int d = 0; d < 6; d++) sp[tt][d] = pack2(h[tt][d], h[tt][d]);
        #pragma unroll
        for (int i2 = 0; i2 < 3; i2++) {
            const ulonglong2* wr = reinterpret_cast<const ulonglong2*>(&s_fw2[blk][i2][0]);
            ulonglong2 w01 = wr[0], w23 = wr[1], w45 = wr[2];
            u64 b = *reinterpret_cast<const u64*>(&s_fb2[blk][i2]);
            #pragma unroll
            for (int tt = 0; tt < 3; tt++) {
                u64 acc = b;
                acc = fma2(sp[tt][0], w01.x, acc); acc = fma2(sp[tt][1], w01.y, acc);
                acc = fma2(sp[tt][2], w23.x, acc); acc = fma2(sp[tt][3], w23.y, acc);
                acc = fma2(sp[tt][4], w45.x, acc); acc = fma2(sp[tt][5], w45.y, acc);
                float2 r = unpack2(acc);
                z[tt][2*i2] = eluf(r.x); z[tt][2*i2+1] = eluf(r.y);
            }
        }
        // ---- LayerNorm (biased var, eps 1e-5), splat result into sp ----
        #pragma unroll
        for (int tt = 0; tt < 3; tt++) {
            float mu = (z[tt][0]+z[tt][1]+z[tt][2]+z[tt][3]+z[tt][4]+z[tt][5]) * (1.f/6.f);
            float var = 0.f;
            #pragma unroll
            for (int i = 0; i < 6; i++) { float d = z[tt][i] - mu; var = fmaf(d, d, var); }
            var *= (1.f/6.f);
            float rs = rsqrtf(var + 1e-5f);
            #pragma unroll
            for (int i = 0; i < 6; i++) {
                float zi = fmaf((z[tt][i] - mu) * rs, s_g[blk][i], s_bb[blk][i]);
                sp[tt][i] = pack2(zi, zi);
            }
        }

        // ---- packed qkv projection (weights hoisted); k/v pairs to shared ----
        u64 qp[3][3];
        __syncthreads();   // prior-block k/v readers done before overwrite
        #pragma unroll
        for (int i2 = 0; i2 < 9; i2++) {
            const ulonglong2* wr = reinterpret_cast<const ulonglong2*>(&s_iw2[blk][i2][0]);
            ulonglong2 w01 = wr[0], w23 = wr[1], w45 = wr[2];
            u64 b = *reinterpret_cast<const u64*>(&s_ib2[blk][i2]);
            #pragma unroll
            for (int tt = 0; tt < 3; tt++) {
                u64 acc = b;
                acc = fma2(sp[tt][0], w01.x, acc); acc = fma2(sp[tt][1], w01.y, acc);
                acc = fma2(sp[tt][2], w23.x, acc); acc = fma2(sp[tt][3], w23.y, acc);
                acc = fma2(sp[tt][4], w45.x, acc); acc = fma2(sp[tt][5], w45.y, acc);
                if (i2 < 3) {
                    qp[tt][i2] = mul2(acc, QS2);
                } else {
                    // record layout: u64[6] = k01,k23,k45,v01,v23,v45
                    u64* rec = reinterpret_cast<u64*>(kvbase + (t + tt * TPI) * 12);
                    rec[i2 - 3] = acc;
                }
            }
        }
        __syncthreads();   // k/v visible to the whole item

        // ---- fused single-pass attention (max-free softmax, packed f32x2) ----
        // FULL unroll: all LDS offsets become immediates, no loop-carried index
        // math, and ptxas gets a flat 54-key window to batch loads and
        // interleave the three query chains.
        u64 o[3][3] = {{0ull,0ull,0ull},{0ull,0ull,0ull},{0ull,0ull,0ull}};
        float sum[3] = {0.f, 0.f, 0.f};
        const ulonglong2* kvp = reinterpret_cast<const ulonglong2*>(kvbase);
        #pragma unroll
        for (int kq = 0; kq < SEQ; kq++) {
            ulonglong2 P0 = kvp[3*kq];      // (k0,k1),(k2,k3)
            ulonglong2 P1 = kvp[3*kq+1];    // (k4,k5),(v0,v1)
            ulonglong2 P2 = kvp[3*kq+2];    // (v2,v3),(v4,v5)
            #pragma unroll
            for (int tt = 0; tt < 3; tt++) {
                u64 d2 = mul2(qp[tt][2], P1.x);
                d2 = fma2(qp[tt][1], P0.y, d2);
                d2 = fma2(qp[tt][0], P0.x, d2);
                float2 dd = unpack2(d2);
                float e = ex2f(dd.x + dd.y);
                sum[tt] += e;
                u64 e2 = pack2(e, e);
                o[tt][0] = fma2(e2, P1.y, o[tt][0]);
                o[tt][1] = fma2(e2, P2.x, o[tt][1]);
                o[tt][2] = fma2(e2, P2.y, o[tt][2]);
            }
        }

        // ---- normalize (splat into sp), out proj + ELU + residual ----
        #pragma unroll
        for (int tt = 0; tt < 3; tt++) {
            float inv = __fdividef(1.f, sum[tt]);
            #pragma unroll
            for (int p = 0; p < 3; p++) {
                float2 d = unpack2(o[tt][p]);
                float a = d.x * inv, bq = d.y * inv;
                sp[tt][2*p]   = pack2(a, a);
                sp[tt][2*p+1] = pack2(bq, bq);
            }
        }
        #pragma unroll
        for (int i2 = 0; i2 < 3; i2++) {
            const ulonglong2* wr = reinterpret_cast<const ulonglong2*>(&s_ow2[blk][i2][0]);
            ulonglong2 w01 = wr[0], w23 = wr[1], w45 = wr[2];
            u64 b = *reinterpret_cast<const u64*>(&s_ob2[blk][i2]);
            #pragma unroll
            for (int tt = 0; tt < 3; tt++) {
                u64 acc = b;
                acc = fma2(sp[tt][0], w01.x, acc); acc = fma2(sp[tt][1], w01.y, acc);
                acc = fma2(sp[tt][2], w23.x, acc); acc = fma2(sp[tt][3], w23.y, acc);
                acc = fma2(sp[tt][4], w45.x, acc); acc = fma2(sp[tt][5], w45.y, acc);
                float2 r = unpack2(acc);
                h[tt][2*i2]   += eluf(r.x);
                h[tt][2*i2+1] += eluf(r.y);
            }
        }
    }

    // ---- heads: stage flattened f[324] into (reused) s_kv, then 13 dot products ----
    __syncthreads();                 // last attention reads of s_kv done
    float* f = kvbase;
    #pragma unroll
    for (int tt = 0; tt < 3; tt++)
        #pragma unroll
        for (int d = 0; d < 6; d++) f[(t + tt * TPI) * 6 + d] = h[tt][d];
    __syncthreads();

    if (t < 13 && live) {
        const float* w = (t < 12) ? (policy_w + t * (SEQ*DIM)) : value_w;
        float acc = (t < 12) ? policy_b[t] : value_b[0];
        const float4* w4 = reinterpret_cast<const float4*>(w);
        const float4* f4 = reinterpret_cast<const float4*>(f);
        #pragma unroll 9
        for (int i = 0; i < (SEQ*DIM)/4; i++) {   // 81 float4s
            float4 a = w4[i]; float4 b = f4[i];
            acc = fmaf(a.x, b.x, acc); acc = fmaf(a.y, b.y, acc);
            acc = fmaf(a.z, b.z, acc); acc = fmaf(a.w, b.w, acc);
        }
        s_lg[g][t] = acc;
    }
    __syncthreads();

    if (live) {
        if (t == 12) out[item] = s_lg[g][12];                   // value head
        if (t < 12) {                                           // policy softmax
            float m = s_lg[g][0];
            #pragma unroll
            for (int j = 1; j < 12; j++) m = fmaxf(m, s_lg[g][j]);
            float sum = 0.f;
            #pragma unroll
            for (int j = 0; j < 12; j++) sum += __expf(s_lg[g][j] - m);
            out[BATCH + item*12 + t] = __expf(s_lg[g][t] - m) / sum;
        }
    }
}

extern "C" void kernel_launch(void* const* d_in, const int* in_sizes, int n_in,
                              void* d_out, int out_size) {
    const float* x        = (const float*)d_in[0];
    const float* embed_w  = (const float*)d_in[1];
    const float* embed_b  = (const float*)d_in[2];
    const float* fc1_w    = (const float*)d_in[3];
    const float* fc1_b    = (const float*)d_in[4];
    const float* ln_g     = (const float*)d_in[5];
    const float* ln_b     = (const float*)d_in[6];
    const float* ipw      = (const float*)d_in[7];
    const float* ipb      = (const float*)d_in[8];
    const float* outw     = (const float*)d_in[9];
    const float* outb     = (const float*)d_in[10];
    const float* value_w  = (const float*)d_in[11];
    const float* value_b  = (const float*)d_in[12];
    const float* policy_w = (const float*)d_in[13];
    const float* policy_b = (const float*)d_in[14];
    float* out = (float*)d_out;

    rubik_kernel<<<GRID, TPB>>>(x, embed_w, embed_b, fc1_w, fc1_b,
                                ln_g, ln_b, ipw, ipb, outw, outb,
                                value_w, value_b, policy_w, policy_b, out);
}

// round 15
// speedup vs baseline: 1.0029x; 1.0029x over previous
#include <cuda_runtime.h>

#define BATCH 65536
#define SEQ 54
#define DIM 6
#define NB 8
#define TPI 18               // threads per item (3 queries each)
#define GG 7                 // items per CTA
#define TPB (GG * TPI)       // 126 threads
#define GRID ((BATCH + GG - 1) / GG)   // 9363
#define KV_STRIDE 648        // floats per item slot (16B-aligned, bank step 8)

typedef unsigned long long u64;

__device__ __forceinline__ float ex2f(float x) {
    float r; asm("ex2.approx.ftz.f32 %0, %1;" : "=f"(r) : "f"(x)); return r;
}
__device__ __forceinline__ u64 fma2(u64 a, u64 b, u64 c) {
    u64 d; asm("fma.rn.f32x2 %0, %1, %2, %3;" : "=l"(d) : "l"(a), "l"(b), "l"(c)); return d;
}
__device__ __forceinline__ u64 mul2(u64 a, u64 b) {
    u64 d; asm("mul.rn.f32x2 %0, %1, %2;" : "=l"(d) : "l"(a), "l"(b)); return d;
}
__device__ __forceinline__ u64 pack2(float lo, float hi) {
    u64 d; asm("mov.b64 %0, {%1, %2};" : "=l"(d)
               : "r"(__float_as_uint(lo)), "r"(__float_as_uint(hi))); return d;
}
__device__ __forceinline__ float2 unpack2(u64 d) {
    unsigned lo, hi; asm("mov.b64 {%0, %1}, %2;" : "=r"(lo), "=r"(hi) : "l"(d));
    return make_float2(__uint_as_float(lo), __uint_as_float(hi));
}
__device__ __forceinline__ float eluf(float x) { return x > 0.f ? x : (__expf(x) - 1.f); }

__global__ void __launch_bounds__(TPB, 6) rubik_kernel(
    const float* __restrict__ x,
    const float* __restrict__ embed_w, const float* __restrict__ embed_b,
    const float* __restrict__ fc1_w,   const float* __restrict__ fc1_b,
    const float* __restrict__ ln_g,    const float* __restrict__ ln_b,
    const float* __restrict__ ipw,     const float* __restrict__ ipb,
    const float* __restrict__ outw,    const float* __restrict__ outb,
    const float* __restrict__ value_w, const float* __restrict__ value_b,
    const float* __restrict__ policy_w,const float* __restrict__ policy_b,
    float* __restrict__ out)
{
    // output-pair-interleaved weights: s_*w2[..][i2][j] = (w[2*i2][j], w[2*i2+1][j])
    __shared__ __align__(16) float2 s_ew2[3][8];
    __shared__ __align__(16) float2 s_eb2[4];
    __shared__ __align__(16) float2 s_fw2[NB][3][8];
    __shared__ __align__(16) float2 s_fb2[NB][4];
    __shared__ float s_g [NB][8];
    __shared__ float s_bb[NB][8];
    __shared__ __align__(16) float2 s_iw2[NB][9][8];
    __shared__ __align__(16) float2 s_ib2[NB][12];
    __shared__ __align__(16) float2 s_ow2[NB][3][8];
    __shared__ __align__(16) float2 s_ob2[NB][4];
    __shared__ __align__(16) float s_kv[GG * KV_STRIDE];
    __shared__ float s_lg[GG][16];

    const int tid = threadIdx.x;

    // ---- cooperative weight staging (pair-interleaved) ----
    for (int i = tid; i < 18; i += TPB) {
        int i2 = i / 6, j = i % 6;
        s_ew2[i2][j] = make_float2(embed_w[(2*i2)*6 + j], embed_w[(2*i2+1)*6 + j]);
    }
    if (tid < 3) s_eb2[tid] = make_float2(embed_b[2*tid], embed_b[2*tid+1]);
    for (int i = tid; i < NB*18; i += TPB) {
        int blk = i / 18, r = i % 18, i2 = r / 6, j = r % 6;
        const float* w = fc1_w + blk * 36;
        s_fw2[blk][i2][j] = make_float2(w[(2*i2)*6 + j], w[(2*i2+1)*6 + j]);
    }
    for (int i = tid; i < NB*3; i += TPB) {
        int blk = i / 3, i2 = i % 3;
        s_fb2[blk][i2] = make_float2(fc1_b[blk*6 + 2*i2], fc1_b[blk*6 + 2*i2 + 1]);
    }
    for (int i = tid; i < NB*6; i += TPB) s_g [i/6][i%6] = ln_g[i];
    for (int i = tid; i < NB*6; i += TPB) s_bb[i/6][i%6] = ln_b[i];
    for (int i = tid; i < NB*54; i += TPB) {
        int blk = i / 54, r = i % 54, i2 = r / 6, j = r % 6;
        const float* w = ipw + blk * 108;
        s_iw2[blk][i2][j] = make_float2(w[(2*i2)*6 + j], w[(2*i2+1)*6 + j]);
    }
    for (int i = tid; i < NB*9; i += TPB) {
        int blk = i / 9, i2 = i % 9;
        s_ib2[blk][i2] = make_float2(ipb[blk*18 + 2*i2], ipb[blk*18 + 2*i2 + 1]);
    }
    for (int i = tid; i < NB*18; i += TPB) {
        int blk = i / 18, r = i % 18, i2 = r / 6, j = r % 6;
        const float* w = outw + blk * 36;
        s_ow2[blk][i2][j] = make_float2(w[(2*i2)*6 + j], w[(2*i2+1)*6 + j]);
    }
    for (int i = tid; i < NB*3; i += TPB) {
        int blk = i / 3, i2 = i % 3;
        s_ob2[blk][i2] = make_float2(outb[blk*6 + 2*i2], outb[blk*6 + 2*i2 + 1]);
    }
    __syncthreads();

    const int g    = tid / TPI;        // item slot within CTA
    const int t    = tid - g * TPI;    // query-thread index, tokens t, t+18, t+36
    const int item = blockIdx.x * GG + g;
    const bool live = (item < BATCH);
    float* kvbase = s_kv + g * KV_STRIDE;

    // fold softmax scale and log2(e) into q
    const float QS = 0.40824829046386302f * 1.4426950408889634f;
    const u64 QS2 = pack2(QS, QS);

    // ---- embed: h = x @ ew^T + eb (3 tokens, packed output pairs) ----
    float h[3][6];
    {
        u64 xs[3][6];
        #pragma unroll
        for (int tt = 0; tt < 3; tt++) {
            const float* xp = x + (item * SEQ + t + tt * TPI) * DIM;
            #pragma unroll
            for (int d = 0; d < 6; d++) {
                float v = live ? xp[d] : 0.f;
                xs[tt][d] = pack2(v, v);
            }
        }
        #pragma unroll
        for (int i2 = 0; i2 < 3; i2++) {
            const ulonglong2* wr = reinterpret_cast<const ulonglong2*>(&s_ew2[i2][0]);
            ulonglong2 w01 = wr[0], w23 = wr[1], w45 = wr[2];
            u64 b = *reinterpret_cast<const u64*>(&s_eb2[i2]);
            #pragma unroll
            for (int tt = 0; tt < 3; tt++) {
                u64 acc = b;
                acc = fma2(xs[tt][0], w01.x, acc); acc = fma2(xs[tt][1], w01.y, acc);
                acc = fma2(xs[tt][2], w23.x, acc); acc = fma2(xs[tt][3], w23.y, acc);
                acc = fma2(xs[tt][4], w45.x, acc); acc = fma2(xs[tt][5], w45.y, acc);
                float2 r = unpack2(acc);
                h[tt][2*i2] = r.x; h[tt][2*i2+1] = r.y;
            }
        }
    }

    for (int blk = 0; blk < NB; blk++) {
        u64 sp[3][6];   // splat buffer (h for fc1, then z for qkv, then ov for out)

        // ---- fc1 + ELU (packed output pairs, weights hoisted) ----
        float z[3][6];
        #pragma unroll
        for (int tt = 0; tt < 3; tt++)
            #pragma unroll
            for (int d = 0; d < 6; d++) sp[tt][d] = pack2(h[tt][d], h[tt][d]);
        #pragma unroll
        for (int i2 = 0; i2 < 3; i2++) {
            const ulonglong2* wr = reinterpret_cast<const ulonglong2*>(&s_fw2[blk][i2][0]);
            ulonglong2 w01 = wr[0], w23 = wr[1], w45 = wr[2];
            u64 b = *reinterpret_cast<const u64*>(&s_fb2[blk][i2]);
            #pragma unroll
            for (int tt = 0; tt < 3; tt++) {
                u64 acc = b;
                acc = fma2(sp[tt][0], w01.x, acc); acc = fma2(sp[tt][1], w01.y, acc);
                acc = fma2(sp[tt][2], w23.x, acc); acc = fma2(sp[tt][3], w23.y, acc);
                acc = fma2(sp[tt][4], w45.x, acc); acc = fma2(sp[tt][5], w45.y, acc);
                float2 r = unpack2(acc);
                z[tt][2*i2] = eluf(r.x); z[tt][2*i2+1] = eluf(r.y);
            }
        }
        // ---- LayerNorm (biased var, eps 1e-5), splat result into sp ----
        #pragma unroll
        for (int tt = 0; tt < 3; tt++) {
            float mu = (z[tt][0]+z[tt][1]+z[tt][2]+z[tt][3]+z[tt][4]+z[tt][5]) * (1.f/6.f);
            float var = 0.f;
            #pragma unroll
            for (int i = 0; i < 6; i++) { float d = z[tt][i] - mu; var = fmaf(d, d, var); }
            var *= (1.f/6.f);
            float rs = rsqrtf(var + 1e-5f);
            #pragma unroll
            for (int i = 0; i < 6; i++) {
                float zi = fmaf((z[tt][i] - mu) * rs, s_g[blk][i], s_bb[blk][i]);
                sp[tt][i] = pack2(zi, zi);
            }
        }

        // ---- packed qkv projection (weights hoisted); k/v pairs to shared ----
        u64 qp[3][3];
        __syncthreads();   // prior-block k/v readers done before overwrite
        #pragma unroll
        for (int i2 = 0; i2 < 9; i2++) {
            const ulonglong2* wr = reinterpret_cast<const ulonglong2*>(&s_iw2[blk][i2][0]);
            ulonglong2 w01 = wr[0], w23 = wr[1], w45 = wr[2];
            u64 b = *reinterpret_cast<const u64*>(&s_ib2[blk][i2]);
            #pragma unroll
            for (int tt = 0; tt < 3; tt++) {
                u64 acc = b;
                acc = fma2(sp[tt][0], w01.x, acc); acc = fma2(sp[tt][1], w01.y, acc);
                acc = fma2(sp[tt][2], w23.x, acc); acc = fma2(sp[tt][3], w23.y, acc);
                acc = fma2(sp[tt][4], w45.x, acc); acc = fma2(sp[tt][5], w45.y, acc);
                if (i2 < 3) {
                    qp[tt][i2] = mul2(acc, QS2);
                } else {
                    // record layout: u64[6] = k01,k23,k45,v01,v23,v45
                    u64* rec = reinterpret_cast<u64*>(kvbase + (t + tt * TPI) * 12);
                    rec[i2 - 3] = acc;
                }
            }
        }
        __syncthreads();   // k/v visible to the whole item

        // ---- fused single-pass attention (max-free softmax, packed f32x2) ----
        u64 o[3][3] = {{0ull,0ull,0ull},{0ull,0ull,0ull},{0ull,0ull,0ull}};
        float sumA[3] = {0.f, 0.f, 0.f};   // dual accumulators: halve the
        float sumB[3] = {0.f, 0.f, 0.f};   // serial FADD chain per query
        const ulonglong2* kvp = reinterpret_cast<const ulonglong2*>(kvbase);
        #pragma unroll 6
        for (int kq = 0; kq < SEQ; kq++) {
            ulonglong2 P0 = kvp[3*kq];      // (k0,k1),(k2,k3)
            ulonglong2 P1 = kvp[3*kq+1];    // (k4,k5),(v0,v1)
            ulonglong2 P2 = kvp[3*kq+2];    // (v2,v3),(v4,v5)
            #pragma unroll
            for (int tt = 0; tt < 3; tt++) {
                u64 d2 = mul2(qp[tt][2], P1.x);
                d2 = fma2(qp[tt][1], P0.y, d2);
                d2 = fma2(qp[tt][0], P0.x, d2);
                float2 dd = unpack2(d2);
                float e = ex2f(dd.x + dd.y);
                if (kq & 1) sumB[tt] += e; else sumA[tt] += e;
                u64 e2 = pack2(e, e);
                o[tt][0] = fma2(e2, P1.y, o[tt][0]);
                o[tt][1] = fma2(e2, P2.x, o[tt][1]);
                o[tt][2] = fma2(e2, P2.y, o[tt][2]);
            }
        }

        // ---- normalize (splat into sp), out proj + ELU + residual ----
        #pragma unroll
        for (int tt = 0; tt < 3; tt++) {
            float inv = __fdividef(1.f, sumA[tt] + sumB[tt]);
            #pragma unroll
            for (int p = 0; p < 3; p++) {
                float2 d = unpack2(o[tt][p]);
                float a = d.x * inv, bq = d.y * inv;
                sp[tt][2*p]   = pack2(a, a);
                sp[tt][2*p+1] = pack2(bq, bq);
            }
        }
        #pragma unroll
        for (int i2 = 0; i2 < 3; i2++) {
            const ulonglong2* wr = reinterpret_cast<const ulonglong2*>(&s_ow2[blk][i2][0]);
            ulonglong2 w01 = wr[0], w23 = wr[1], w45 = wr[2];
            u64 b = *reinterpret_cast<const u64*>(&s_ob2[blk][i2]);
            #pragma unroll
            for (int tt = 0; tt < 3; tt++) {
                u64 acc = b;
                acc = fma2(sp[tt][0], w01.x, acc); acc = fma2(sp[tt][1], w01.y, acc);
                acc = fma2(sp[tt][2], w23.x, acc); acc = fma2(sp[tt][3], w23.y, acc);
                acc = fma2(sp[tt][4], w45.x, acc); acc = fma2(sp[tt][5], w45.y, acc);
                float2 r = unpack2(acc);
                h[tt][2*i2]   += eluf(r.x);
                h[tt][2*i2+1] += eluf(r.y);
            }
        }
    }

    // ---- heads: stage flattened f[324] into (reused) s_kv, then 13 dot products ----
    __syncthreads();                 // last attention reads of s_kv done
    float* f = kvbase;
    #pragma unroll
    for (int tt = 0; tt < 3; tt++)
        #pragma unroll
        for (int d = 0; d < 6; d++) f[(t + tt * TPI) * 6 + d] = h[tt][d];
    __syncthreads();

    if (t < 13 && live) {
        const float* w = (t < 12) ? (policy_w + t * (SEQ*DIM)) : value_w;
        float acc = (t < 12) ? policy_b[t] : value_b[0];
        const float4* w4 = reinterpret_cast<const float4*>(w);
        const float4* f4 = reinterpret_cast<const float4*>(f);
        #pragma unroll 9
        for (int i = 0; i < (SEQ*DIM)/4; i++) {   // 81 float4s
            float4 a = w4[i]; float4 b = f4[i];
            acc = fmaf(a.x, b.x, acc); acc = fmaf(a.y, b.y, acc);
            acc = fmaf(a.z, b.z, acc); acc = fmaf(a.w, b.w, acc);
        }
        s_lg[g][t] = acc;
    }
    __syncthreads();

    if (live) {
        if (t == 12) out[item] = s_lg[g][12];                   // value head
        if (t < 12) {                                           // policy softmax
            float m = s_lg[g][0];
            #pragma unroll
            for (int j = 1; j < 12; j++) m = fmaxf(m, s_lg[g][j]);
            float sum = 0.f;
            #pragma unroll
            for (int j = 0; j < 12; j++) sum += __expf(s_lg[g][j] - m);
            out[BATCH + item*12 + t] = __expf(s_lg[g][t] - m) / sum;
        }
    }
}

extern "C" void kernel_launch(void* const* d_in, const int* in_sizes, int n_in,
                              void* d_out, int out_size) {
    const float* x        = (const float*)d_in[0];
    const float* embed_w  = (const float*)d_in[1];
    const float* embed_b  = (const float*)d_in[2];
    const float* fc1_w    = (const float*)d_in[3];
    const float* fc1_b    = (const float*)d_in[4];
    const float* ln_g     = (const float*)d_in[5];
    const float* ln_b     = (const float*)d_in[6];
    const float* ipw      = (const float*)d_in[7];
    const float* ipb      = (const float*)d_in[8];
    const float* outw     = (const float*)d_in[9];
    const float* outb     = (const float*)d_in[10];
    const float* value_w  = (const float*)d_in[11];
    const float* value_b  = (const float*)d_in[12];
    const float* policy_w = (const float*)d_in[13];
    const float* policy_b = (const float*)d_in[14];
    float* out = (float*)d_out;

    rubik_kernel<<<GRID, TPB>>>(x, embed_w, embed_b, fc1_w, fc1_b,
                                ln_g, ln_b, ipw, ipb, outw, outb,
                                value_w, value_b, policy_w, policy_b, out);
}

// round 16
// speedup vs baseline: 1.0111x; 1.0081x over previous
#include <cuda_runtime.h>

#define BATCH 65536
#define SEQ 54
#define DIM 6
#define NB 8
#define TPI 18               // threads per item (3 queries each)
#define GG 7                 // items per CTA
#define TPB (GG * TPI)       // 126 threads
#define GRID ((BATCH + GG - 1) / GG)   // 9363
#define KV_STRIDE 660        // floats per item slot (16B-aligned, bank step 20)

typedef unsigned long long u64;

__device__ __forceinline__ float ex2f(float x) {
    float r; asm("ex2.approx.ftz.f32 %0, %1;" : "=f"(r) : "f"(x)); return r;
}
__device__ __forceinline__ u64 fma2(u64 a, u64 b, u64 c) {
    u64 d; asm("fma.rn.f32x2 %0, %1, %2, %3;" : "=l"(d) : "l"(a), "l"(b), "l"(c)); return d;
}
__device__ __forceinline__ u64 mul2(u64 a, u64 b) {
    u64 d; asm("mul.rn.f32x2 %0, %1, %2;" : "=l"(d) : "l"(a), "l"(b)); return d;
}
__device__ __forceinline__ u64 pack2(float lo, float hi) {
    u64 d; asm("mov.b64 %0, {%1, %2};" : "=l"(d)
               : "r"(__float_as_uint(lo)), "r"(__float_as_uint(hi))); return d;
}
__device__ __forceinline__ float2 unpack2(u64 d) {
    unsigned lo, hi; asm("mov.b64 {%0, %1}, %2;" : "=r"(lo), "=r"(hi) : "l"(d));
    return make_float2(__uint_as_float(lo), __uint_as_float(hi));
}
__device__ __forceinline__ float eluf(float x) { return x > 0.f ? x : (__expf(x) - 1.f); }

__global__ void __launch_bounds__(TPB, 6) rubik_kernel(
    const float* __restrict__ x,
    const float* __restrict__ embed_w, const float* __restrict__ embed_b,
    const float* __restrict__ fc1_w,   const float* __restrict__ fc1_b,
    const float* __restrict__ ln_g,    const float* __restrict__ ln_b,
    const float* __restrict__ ipw,     const float* __restrict__ ipb,
    const float* __restrict__ outw,    const float* __restrict__ outb,
    const float* __restrict__ value_w, const float* __restrict__ value_b,
    const float* __restrict__ policy_w,const float* __restrict__ policy_b,
    float* __restrict__ out)
{
    // output-pair-interleaved weights: s_*w2[..][i2][j] = (w[2*i2][j], w[2*i2+1][j])
    __shared__ __align__(16) float2 s_ew2[3][8];
    __shared__ __align__(16) float2 s_eb2[4];
    __shared__ __align__(16) float2 s_fw2[NB][3][8];
    __shared__ __align__(16) float2 s_fb2[NB][4];
    __shared__ float s_g [NB][8];
    __shared__ float s_bb[NB][8];
    __shared__ __align__(16) float2 s_iw2[NB][9][8];
    __shared__ __align__(16) float2 s_ib2[NB][12];
    __shared__ __align__(16) float2 s_ow2[NB][3][8];
    __shared__ __align__(16) float2 s_ob2[NB][4];
    __shared__ __align__(16) float s_kv[GG * KV_STRIDE];
    __shared__ float s_lg[GG][16];

    const int tid = threadIdx.x;

    // ---- cooperative weight staging (pair-interleaved) ----
    for (int i = tid; i < 18; i += TPB) {
        int i2 = i / 6, j = i % 6;
        s_ew2[i2][j] = make_float2(embed_w[(2*i2)*6 + j], embed_w[(2*i2+1)*6 + j]);
    }
    if (tid < 3) s_eb2[tid] = make_float2(embed_b[2*tid], embed_b[2*tid+1]);
    for (int i = tid; i < NB*18; i += TPB) {
        int blk = i / 18, r = i % 18, i2 = r / 6, j = r % 6;
        const float* w = fc1_w + blk * 36;
        s_fw2[blk][i2][j] = make_float2(w[(2*i2)*6 + j], w[(2*i2+1)*6 + j]);
    }
    for (int i = tid; i < NB*3; i += TPB) {
        int blk = i / 3, i2 = i % 3;
        s_fb2[blk][i2] = make_float2(fc1_b[blk*6 + 2*i2], fc1_b[blk*6 + 2*i2 + 1]);
    }
    for (int i = tid; i < NB*6; i += TPB) s_g [i/6][i%6] = ln_g[i];
    for (int i = tid; i < NB*6; i += TPB) s_bb[i/6][i%6] = ln_b[i];
    for (int i = tid; i < NB*54; i += TPB) {
        int blk = i / 54, r = i % 54, i2 = r / 6, j = r % 6;
        const float* w = ipw + blk * 108;
        s_iw2[blk][i2][j] = make_float2(w[(2*i2)*6 + j], w[(2*i2+1)*6 + j]);
    }
    for (int i = tid; i < NB*9; i += TPB) {
        int blk = i / 9, i2 = i % 9;
        s_ib2[blk][i2] = make_float2(ipb[blk*18 + 2*i2], ipb[blk*18 + 2*i2 + 1]);
    }
    for (int i = tid; i < NB*18; i += TPB) {
        int blk = i / 18, r = i % 18, i2 = r / 6, j = r % 6;
        const float* w = outw + blk * 36;
        s_ow2[blk][i2][j] = make_float2(w[(2*i2)*6 + j], w[(2*i2+1)*6 + j]);
    }
    for (int i = tid; i < NB*3; i += TPB) {
        int blk = i / 3, i2 = i % 3;
        s_ob2[blk][i2] = make_float2(outb[blk*6 + 2*i2], outb[blk*6 + 2*i2 + 1]);
    }
    __syncthreads();

    const int g    = tid / TPI;        // item slot within CTA
    const int t    = tid - g * TPI;    // query-thread index, tokens t, t+18, t+36
    const int item = blockIdx.x * GG + g;
    const bool live = (item < BATCH);
    float* kvbase = s_kv + g * KV_STRIDE;

    // fold softmax scale and log2(e) into q
    const float QS = 0.40824829046386302f * 1.4426950408889634f;
    const u64 QS2 = pack2(QS, QS);

    // ---- embed: h = x @ ew^T + eb (3 tokens, packed output pairs) ----
    float h[3][6];
    {
        u64 xs[3][6];
        #pragma unroll
        for (int tt = 0; tt < 3; tt++) {
            const float* xp = x + (item * SEQ + t + tt * TPI) * DIM;
            #pragma unroll
            for (int d = 0; d < 6; d++) {
                float v = live ? xp[d] : 0.f;
                xs[tt][d] = pack2(v, v);
            }
        }
        #pragma unroll
        for (int i2 = 0; i2 < 3; i2++) {
            const ulonglong2* wr = reinterpret_cast<const ulonglong2*>(&s_ew2[i2][0]);
            ulonglong2 w01 = wr[0], w23 = wr[1], w45 = wr[2];
            u64 b = *reinterpret_cast<const u64*>(&s_eb2[i2]);
            #pragma unroll
            for (int tt = 0; tt < 3; tt++) {
                u64 acc = b;
                acc = fma2(xs[tt][0], w01.x, acc); acc = fma2(xs[tt][1], w01.y, acc);
                acc = fma2(xs[tt][2], w23.x, acc); acc = fma2(xs[tt][3], w23.y, acc);
                acc = fma2(xs[tt][4], w45.x, acc); acc = fma2(xs[tt][5], w45.y, acc);
                float2 r = unpack2(acc);
                h[tt][2*i2] = r.x; h[tt][2*i2+1] = r.y;
            }
        }
    }

    for (int blk = 0; blk < NB; blk++) {
        u64 sp[3][6];   // splat buffer (h for fc1, then z for qkv, then ov for out)

        // ---- fc1 + ELU (packed output pairs, weights hoisted) ----
        float z[3][6];
        #pragma unroll
        for (int tt = 0; tt < 3; tt++)
            #pragma unroll
            for (int d = 0; d < 6; d++) sp[tt][d] = pack2(h[tt][d], h[tt][d]);
        #pragma unroll
        for (int i2 = 0; i2 < 3; i2++) {
            const ulonglong2* wr = reinterpret_cast<const ulonglong2*>(&s_fw2[blk][i2][0]);
            ulonglong2 w01 = wr[0], w23 = wr[1], w45 = wr[2];
            u64 b = *reinterpret_cast<const u64*>(&s_fb2[blk][i2]);
            #pragma unroll
            for (int tt = 0; tt < 3; tt++) {
                u64 acc = b;
                acc = fma2(sp[tt][0], w01.x, acc); acc = fma2(sp[tt][1], w01.y, acc);
                acc = fma2(sp[tt][2], w23.x, acc); acc = fma2(sp[tt][3], w23.y, acc);
                acc = fma2(sp[tt][4], w45.x, acc); acc = fma2(sp[tt][5], w45.y, acc);
                float2 r = unpack2(acc);
                z[tt][2*i2] = eluf(r.x); z[tt][2*i2+1] = eluf(r.y);
            }
        }
        // ---- LayerNorm (biased var, eps 1e-5), splat result into sp ----
        #pragma unroll
        for (int tt = 0; tt < 3; tt++) {
            float mu = (z[tt][0]+z[tt][1]+z[tt][2]+z[tt][3]+z[tt][4]+z[tt][5]) * (1.f/6.f);
            float var = 0.f;
            #pragma unroll
            for (int i = 0; i < 6; i++) { float d = z[tt][i] - mu; var = fmaf(d, d, var); }
            var *= (1.f/6.f);
            float rs = rsqrtf(var + 1e-5f);
            #pragma unroll
            for (int i = 0; i < 6; i++) {
                float zi = fmaf((z[tt][i] - mu) * rs, s_g[blk][i], s_bb[blk][i]);
                sp[tt][i] = pack2(zi, zi);
            }
        }

        // ---- packed qkv projection (weights hoisted); k/v pairs to shared ----
        u64 qp[3][3];
        __syncthreads();   // prior-block k/v readers done before overwrite
        #pragma unroll
        for (int i2 = 0; i2 < 9; i2++) {
            const ulonglong2* wr = reinterpret_cast<const ulonglong2*>(&s_iw2[blk][i2][0]);
            ulonglong2 w01 = wr[0], w23 = wr[1], w45 = wr[2];
            u64 b = *reinterpret_cast<const u64*>(&s_ib2[blk][i2]);
            #pragma unroll
            for (int tt = 0; tt < 3; tt++) {
                u64 acc = b;
                acc = fma2(sp[tt][0], w01.x, acc); acc = fma2(sp[tt][1], w01.y, acc);
                acc = fma2(sp[tt][2], w23.x, acc); acc = fma2(sp[tt][3], w23.y, acc);
                acc = fma2(sp[tt][4], w45.x, acc); acc = fma2(sp[tt][5], w45.y, acc);
                if (i2 < 3) {
                    qp[tt][i2] = mul2(acc, QS2);
                } else {
                    // record layout: u64[6] = k01,k23,k45,v01,v23,v45
                    u64* rec = reinterpret_cast<u64*>(kvbase + (t + tt * TPI) * 12);
                    rec[i2 - 3] = acc;
                }
            }
        }
        __syncthreads();   // k/v visible to the whole item

        // ---- fused single-pass attention (max-free softmax, packed f32x2) ----
        u64 o[3][3] = {{0ull,0ull,0ull},{0ull,0ull,0ull},{0ull,0ull,0ull}};
        float sum[3] = {0.f, 0.f, 0.f};
        const ulonglong2* kvp = reinterpret_cast<const ulonglong2*>(kvbase);
        #pragma unroll 6
        for (int kq = 0; kq < SEQ; kq++) {
            ulonglong2 P0 = kvp[3*kq];      // (k0,k1),(k2,k3)
            ulonglong2 P1 = kvp[3*kq+1];    // (k4,k5),(v0,v1)
            ulonglong2 P2 = kvp[3*kq+2];    // (v2,v3),(v4,v5)
            #pragma unroll
            for (int tt = 0; tt < 3; tt++) {
                u64 d2 = mul2(qp[tt][2], P1.x);
                d2 = fma2(qp[tt][1], P0.y, d2);
                d2 = fma2(qp[tt][0], P0.x, d2);
                float2 dd = unpack2(d2);
                float e = ex2f(dd.x + dd.y);
                sum[tt] += e;
                u64 e2 = pack2(e, e);
                o[tt][0] = fma2(e2, P1.y, o[tt][0]);
                o[tt][1] = fma2(e2, P2.x, o[tt][1]);
                o[tt][2] = fma2(e2, P2.y, o[tt][2]);
            }
        }

        // ---- normalize (splat into sp), out proj + ELU + residual ----
        #pragma unroll
        for (int tt = 0; tt < 3; tt++) {
            float inv = __fdividef(1.f, sum[tt]);
            #pragma unroll
            for (int p = 0; p < 3; p++) {
                float2 d = unpack2(o[tt][p]);
                float a = d.x * inv, bq = d.y * inv;
                sp[tt][2*p]   = pack2(a, a);
                sp[tt][2*p+1] = pack2(bq, bq);
            }
        }
        #pragma unroll
        for (int i2 = 0; i2 < 3; i2++) {
            const ulonglong2* wr = reinterpret_cast<const ulonglong2*>(&s_ow2[blk][i2][0]);
            ulonglong2 w01 = wr[0], w23 = wr[1], w45 = wr[2];
            u64 b = *reinterpret_cast<const u64*>(&s_ob2[blk][i2]);
            #pragma unroll
            for (int tt = 0; tt < 3; tt++) {
                u64 acc = b;
                acc = fma2(sp[tt][0], w01.x, acc); acc = fma2(sp[tt][1], w01.y, acc);
                acc = fma2(sp[tt][2], w23.x, acc); acc = fma2(sp[tt][3], w23.y, acc);
                acc = fma2(sp[tt][4], w45.x, acc); acc = fma2(sp[tt][5], w45.y, acc);
                float2 r = unpack2(acc);
                h[tt][2*i2]   += eluf(r.x);
                h[tt][2*i2+1] += eluf(r.y);
            }
        }
    }

    // ---- heads: stage flattened f[324] into (reused) s_kv, then 13 dot products ----
    __syncthreads();                 // last attention reads of s_kv done
    float* f = kvbase;
    #pragma unroll
    for (int tt = 0; tt < 3; tt++)
        #pragma unroll
        for (int d = 0; d < 6; d++) f[(t + tt * TPI) * 6 + d] = h[tt][d];
    __syncthreads();

    if (t < 13 && live) {
        const float* w = (t < 12) ? (policy_w + t * (SEQ*DIM)) : value_w;
        float acc = (t < 12) ? policy_b[t] : value_b[0];
        const float4* w4 = reinterpret_cast<const float4*>(w);
        const float4* f4 = reinterpret_cast<const float4*>(f);
        #pragma unroll 9
        for (int i = 0; i < (SEQ*DIM)/4; i++) {   // 81 float4s
            float4 a = w4[i]; float4 b = f4[i];
            acc = fmaf(a.x, b.x, acc); acc = fmaf(a.y, b.y, acc);
            acc = fmaf(a.z, b.z, acc); acc = fmaf(a.w, b.w, acc);
        }
        s_lg[g][t] = acc;
    }
    __syncthreads();

    if (live) {
        if (t == 12) out[item] = s_lg[g][12];                   // value head
        if (t < 12) {                                           // policy softmax
            float m = s_lg[g][0];
            #pragma unroll
            for (int j = 1; j < 12; j++) m = fmaxf(m, s_lg[g][j]);
            float sum = 0.f;
            #pragma unroll
            for (int j = 0; j < 12; j++) sum += __expf(s_lg[g][j] - m);
            out[BATCH + item*12 + t] = __expf(s_lg[g][t] - m) / sum;
        }
    }
}

extern "C" void kernel_launch(void* const* d_in, const int* in_sizes, int n_in,
                              void* d_out, int out_size) {
    const float* x        = (const float*)d_in[0];
    const float* embed_w  = (const float*)d_in[1];
    const float* embed_b  = (const float*)d_in[2];
    const float* fc1_w    = (const float*)d_in[3];
    const float* fc1_b    = (const float*)d_in[4];
    const float* ln_g     = (const float*)d_in[5];
    const float* ln_b     = (const float*)d_in[6];
    const float* ipw      = (const float*)d_in[7];
    const float* ipb      = (const float*)d_in[8];
    const float* outw     = (const float*)d_in[9];
    const float* outb     = (const float*)d_in[10];
    const float* value_w  = (const float*)d_in[11];
    const float* value_b  = (const float*)d_in[12];
    const float* policy_w = (const float*)d_in[13];
    const float* policy_b = (const float*)d_in[14];
    float* out = (float*)d_out;

    rubik_kernel<<<GRID, TPB>>>(x, embed_w, embed_b, fc1_w, fc1_b,
                                ln_g, ln_b, ipw, ipb, outw, outb,
                                value_w, value_b, policy_w, policy_b, out);
}